// round 1
// baseline (speedup 1.0000x reference)
#include <cuda_runtime.h>

#define NN     512
#define LROWS  4
#define NCTA   (NN / LROWS)   // 128 CTAs, all resident in wave 1 (<= 148 SMs)
#define NTH    512            // thread t <-> column t

// Persistent-kernel state (device globals: allocation-free).
__device__ float g_rows[NN * NN];   // row k as published at step k (written once per run)
__device__ int   g_front;           // frontier: rows [0, g_front) are published
__device__ int   g_done;            // completion counter for end-of-run reset
__device__ float g_part[NCTA * 4];  // per-CTA partials: cost, util, entropy, mask

static __device__ __forceinline__ float fex2(float x) {
    float y; asm("ex2.approx.f32 %0, %1;" : "=f"(y) : "f"(x)); return y;
}
static __device__ __forceinline__ float flg2(float x) {
    float y; asm("lg2.approx.f32 %0, %1;" : "=f"(y) : "f"(x)); return y;
}
static __device__ __forceinline__ int ld_acq(const int* p) {
    int v; asm volatile("ld.acquire.gpu.b32 %0, [%1];" : "=r"(v) : "l"(p) : "memory"); return v;
}
static __device__ __forceinline__ void st_rel(int* p, int v) {
    asm volatile("st.release.gpu.b32 [%0], %1;" :: "l"(p), "r"(v) : "memory");
}

__global__ void __launch_bounds__(NTH, 1) fw_kernel(
    const float* __restrict__ soft, const float* __restrict__ orig,
    const float* __restrict__ dist, const float* __restrict__ flow)
{
    __shared__ float a_s[LROWS];     // old w[r][k] for this CTA's rows (column-k broadcast)
    __shared__ float r4[16][4];      // reduction buffer

    const int t    = threadIdx.x;    // column index
    const int cta  = blockIdx.x;
    const int r0   = cta * LROWS;
    const int lane = t & 31;
    const int wid  = t >> 5;

    // W rows live entirely in registers: wv[lr] = W[r0+lr][t]
    float wv[LROWS], dv[LROWS];
    float accC = 0.f, accM = 0.f, accE = 0.f;
#pragma unroll
    for (int lr = 0; lr < LROWS; lr++) {
        int r   = r0 + lr;
        float s = soft[r * NN + t];
        float d = dist[r * NN + t];
        float o = orig[r * NN + t];
        dv[lr]  = d;
        wv[lr]  = (r == t) ? 0.f : (d / (s + 1e-4f));   // W0, zeroed diagonal
        accC    = fmaf(s, d, accC);                     // loss_cost
        accM    = fmaf(s, 1.f - o, accM);               // mask_loss
        float z = s * (((r == t) ? 1.f : 0.f) - s);     // soft*(I - soft)
        accE    = fmaf(z, z, accE);                     // entropy
    }

    const float C1 = 14.4269504088896f;  // log2(e)/gamma
    const float C2 = 0.069314718055995f; // gamma*ln2

    // Preload row 0 element for non-owners.
    float rk_cur = 0.f;
    int   front  = 0;
    if (cta != 0) {
        int spin = 0;
        while (front < 1 && spin < (1 << 30)) { front = ld_acq(&g_front); spin++; }
        rk_cur = __ldcg(&g_rows[t]);
    }

    for (int k = 0; k < NN; k++) {
        __syncthreads();   // B1: prior step's a_s reads done before overwrite
        if (t == k) {
#pragma unroll
            for (int lr = 0; lr < LROWS; lr++) a_s[lr] = wv[lr];  // old column-k values
        }
        int  lrk = k - r0;
        bool own = (lrk >= 0) && (lrk < LROWS);
        if (own) {
            float v = (lrk == 0) ? wv[0] : (lrk == 1) ? wv[1] : (lrk == 2) ? wv[2] : wv[3];
            g_rows[k * NN + t] = v;   // publish OLD row k (each thread stores its own column)
            rk_cur = v;
        }
        __syncthreads();   // B2: a_s + g_rows stores complete
        if (own && t == 0) st_rel(&g_front, k + 1);   // release: row k now visible

        // Early (non-blocking) prefetch attempt for row k+1 — hides L2 latency
        const int kn   = k + 1;
        int  lrn       = kn - r0;
        bool own_n     = (lrn >= 0) && (lrn < LROWS);
        bool need      = (kn < NN) && (!own_n);
        float rk_nxt   = 0.f;
        bool  got      = false;
        if (need) {
            if (front <= kn) front = ld_acq(&g_front);   // coalesced same-address load
            if (front > kn) { rk_nxt = __ldcg(&g_rows[kn * NN + t]); got = true; }
        }

        // Softmin update for this thread's 4 elements (all in registers)
#pragma unroll
        for (int lr = 0; lr < LROWS; lr++) {
            float a = a_s[lr];          // old w[r][k]  (SMEM broadcast)
            float p = a + rk_cur;       // old w[r][k] + old w[k][t]
            float w = wv[lr];
            float m = fminf(w, p);
            float e = fex2(-fabsf(w - p) * C1);
            float l = flg2(1.0f + e);
            wv[lr]  = fmaf(-C2, l, m);  // min - gamma*ln2*log2(1+2^(-|d|/(g*ln2)))
        }

        if (need) {
            if (!got) {   // frontier-adjacent: block until row k+1 published
                int spin = 0;
                do { front = ld_acq(&g_front); spin++; } while (front <= kn && spin < (1 << 30));
                rk_nxt = __ldcg(&g_rows[kn * NN + t]);
            }
            rk_cur = rk_nxt;
        }
    }
    __syncthreads();

    // Epilogue: utility term from shortest paths (still in registers)
    float accU = 0.f;
#pragma unroll
    for (int lr = 0; lr < LROWS; lr++) {
        int r    = r0 + lr;
        float d  = dv[lr];
        float f  = flow[r * NN + t];
        float sp = wv[lr];
        // er/(er+eb) = 1/(1+exp(0.005*sp - 0.01*d)); handles underflow like the reference
        float choice = 1.0f / (1.0f + expf(fmaf(0.005f, sp, -0.01f * d)));
        float ds  = fmaf(-0.5f, sp, d);
        float ug  = f * choice * ds;
        float elu = (ug > 0.f) ? ug : (expf(ug) - 1.0f);
        accU += elu + 1.0f;
    }

    // CTA reduction of the four partials
#pragma unroll
    for (int o = 16; o > 0; o >>= 1) {
        accC += __shfl_down_sync(0xffffffffu, accC, o);
        accU += __shfl_down_sync(0xffffffffu, accU, o);
        accE += __shfl_down_sync(0xffffffffu, accE, o);
        accM += __shfl_down_sync(0xffffffffu, accM, o);
    }
    if (lane == 0) { r4[wid][0] = accC; r4[wid][1] = accU; r4[wid][2] = accE; r4[wid][3] = accM; }
    __syncthreads();
    if (t < 16) {
        float a = r4[t][0], b = r4[t][1], c = r4[t][2], d = r4[t][3];
#pragma unroll
        for (int o = 8; o > 0; o >>= 1) {
            a += __shfl_down_sync(0xffffu, a, o);
            b += __shfl_down_sync(0xffffu, b, o);
            c += __shfl_down_sync(0xffffu, c, o);
            d += __shfl_down_sync(0xffffu, d, o);
        }
        if (t == 0) {
            g_part[cta * 4 + 0] = a; g_part[cta * 4 + 1] = b;
            g_part[cta * 4 + 2] = c; g_part[cta * 4 + 3] = d;
        }
    }

    // End-of-run state reset (last CTA) so the next graph replay starts clean.
    __threadfence();
    __syncthreads();
    if (t == 0) {
        int prev = atomicAdd(&g_done, 1);
        if (prev == NCTA - 1) {
            g_front = 0;
            __threadfence();
            g_done = 0;
        }
    }
}

__global__ void fin_kernel(const int* __restrict__ ep, float* __restrict__ out)
{
    const int t = threadIdx.x;           // 128 threads = NCTA
    const int lane = t & 31, wid = t >> 5;
    __shared__ float s4[4][4];
    float c = g_part[t * 4 + 0], u = g_part[t * 4 + 1];
    float e = g_part[t * 4 + 2], m = g_part[t * 4 + 3];
#pragma unroll
    for (int o = 16; o > 0; o >>= 1) {
        c += __shfl_down_sync(0xffffffffu, c, o);
        u += __shfl_down_sync(0xffffffffu, u, o);
        e += __shfl_down_sync(0xffffffffu, e, o);
        m += __shfl_down_sync(0xffffffffu, m, o);
    }
    if (lane == 0) { s4[wid][0] = c; s4[wid][1] = u; s4[wid][2] = e; s4[wid][3] = m; }
    __syncthreads();
    if (t == 0) {
        float C = s4[0][0] + s4[1][0] + s4[2][0] + s4[3][0];
        float U = s4[0][1] + s4[1][1] + s4[2][1] + s4[3][1];
        float E = s4[0][2] + s4[1][2] + s4[2][2] + s4[3][2];
        float M = s4[0][3] + s4[1][3] + s4[2][3] + s4[3][3];
        int epoch = *ep;
        int idx = (epoch >= 0) + (epoch >= 10) + (epoch >= 50);   // bisect_right([0,10,50], epoch)
        const float lv[4] = {0.0f, 0.05f, 0.1f, 1.0f};
        out[0] = C + U + lv[idx] * E + 10000.0f * M;
    }
}

extern "C" void kernel_launch(void* const* d_in, const int* in_sizes, int n_in,
                              void* d_out, int out_size)
{
    (void)in_sizes; (void)n_in; (void)out_size;
    const float* soft = (const float*)d_in[0];
    const float* orig = (const float*)d_in[1];
    const float* dist = (const float*)d_in[2];
    const float* flow = (const float*)d_in[3];
    const int*   ep   = (const int*)d_in[4];

    fw_kernel<<<NCTA, NTH>>>(soft, orig, dist, flow);
    fin_kernel<<<1, NCTA>>>(ep, (float*)d_out);
}

// round 2
// speedup vs baseline: 1.1175x; 1.1175x over previous
#include <cuda_runtime.h>

#define NN     512
#define LROWS  4
#define NCTA   (NN / LROWS)   // 128 CTAs, all resident in wave 1
#define NTH    512            // thread t <-> column t
#define PFD    8              // prefetch group depth (rows)

// Persistent-kernel state (device globals: allocation-free).
__device__ float g_rows[NN * NN];   // row k as published at step k (written once per run)
__device__ int   g_front;           // frontier: rows [0, g_front) are published
__device__ int   g_done;            // completion counter for end-of-run reset
__device__ float g_part[NCTA * 4];  // per-CTA partials: cost, util, entropy, mask

static __device__ __forceinline__ float fex2(float x) {
    float y; asm("ex2.approx.f32 %0, %1;" : "=f"(y) : "f"(x)); return y;
}
static __device__ __forceinline__ float flg2(float x) {
    float y; asm("lg2.approx.f32 %0, %1;" : "=f"(y) : "f"(x)); return y;
}
static __device__ __forceinline__ int ld_acq(const int* p) {
    int v; asm volatile("ld.acquire.gpu.b32 %0, [%1];" : "=r"(v) : "l"(p) : "memory"); return v;
}
static __device__ __forceinline__ void st_rel(int* p, int v) {
    asm volatile("st.release.gpu.b32 [%0], %1;" :: "l"(p), "r"(v) : "memory");
}

__global__ void __launch_bounds__(NTH, 1) fw_kernel(
    const float* __restrict__ soft, const float* __restrict__ orig,
    const float* __restrict__ dist, const float* __restrict__ flow)
{
    __shared__ float a_s[2][LROWS];  // parity-double-buffered column-k broadcast
    __shared__ float r4[16][4];      // reduction buffer

    const int t    = threadIdx.x;    // column index
    const int cta  = blockIdx.x;
    const int r0   = cta * LROWS;
    const int lane = t & 31;
    const int wid  = t >> 5;

    // W rows live entirely in registers: wv[lr] = W[r0+lr][t]
    float wv[LROWS], dv[LROWS];
    float accC = 0.f, accM = 0.f, accE = 0.f;
#pragma unroll
    for (int lr = 0; lr < LROWS; lr++) {
        int r   = r0 + lr;
        float s = soft[r * NN + t];
        float d = dist[r * NN + t];
        float o = orig[r * NN + t];
        dv[lr]  = d;
        wv[lr]  = (r == t) ? 0.f : (d / (s + 1e-4f));   // W0, zeroed diagonal
        accC    = fmaf(s, d, accC);                     // loss_cost
        accM    = fmaf(s, 1.f - o, accM);               // mask_loss
        float z = s * (((r == t) ? 1.f : 0.f) - s);     // soft*(I - soft)
        accE    = fmaf(z, z, accE);                     // entropy
    }

    const float C1 = 14.4269504088896f;  // log2(e)/gamma
    const float C2 = 0.069314718055995f; // gamma*ln2

    int front = 0;                       // cached frontier (per-thread)
    float ringA[PFD], ringB[PFD];
    bool  bulkA = false, bulkB = false;

    // Try to batch-prefetch rows [kg, kg+PFD) into ring (only if all published).
    auto fetch_grp = [&](float (&ring)[PFD], bool &bulkf, int kg) {
        if (kg >= NN) { bulkf = false; return; }
        if (front < kg + PFD) front = ld_acq(&g_front);
        bulkf = (front >= kg + PFD);
        if (bulkf) {
#pragma unroll
            for (int i = 0; i < PFD; i++)
                ring[i] = __ldcg(&g_rows[(kg + i) * NN + t]);
        }
    };

    // Consume rows [kg, kg+PFD): one FW softmin step per row.
    auto consume_grp = [&](float (&ring)[PFD], bool bulkf, int kg) {
#pragma unroll
        for (int i = 0; i < PFD; i++) {
            const int k   = kg + i;
            const int p   = k & 1;
            const int lrk = k - r0;
            const bool own = (lrk >= 0) && (lrk < LROWS);

            if (t == k) {
#pragma unroll
                for (int lr = 0; lr < LROWS; lr++) a_s[p][lr] = wv[lr];
            }

            float rk;
            if (own) {
                float v = (lrk == 0) ? wv[0] : (lrk == 1) ? wv[1]
                        : (lrk == 2) ? wv[2] : wv[3];
                g_rows[k * NN + t] = rk = v;     // publish OLD row k
            } else if (bulkf) {
                rk = ring[i];                    // prefetched, latency hidden
            } else {
                // frontier-adjacent slow path: wait for row k
                if (front <= k) { do { front = ld_acq(&g_front); } while (front <= k); }
                rk = __ldcg(&g_rows[k * NN + t]);
            }

            __syncthreads();                     // a_s[p] + g_rows publish visible in-CTA
            if (own && t == 0) st_rel(&g_front, k + 1);

#pragma unroll
            for (int lr = 0; lr < LROWS; lr++) {
                float a = a_s[p][lr];            // old w[r][k]
                float pp = a + rk;               // old w[r][k] + old w[k][t]
                float w  = wv[lr];
                float m  = fminf(w, pp);
                float e  = fex2(-fabsf(w - pp) * C1);
                float l  = flg2(1.0f + e);
                wv[lr]   = fmaf(-C2, l, m);
            }
        }
    };

    // Software-pipelined group loop: prefetch next group while consuming current.
    fetch_grp(ringA, bulkA, 0);
    for (int kg = 0; kg < NN; kg += 2 * PFD) {
        fetch_grp(ringB, bulkB, kg + PFD);
        if (!bulkA) fetch_grp(ringA, bulkA, kg);          // late recheck (frontier may have advanced)
        consume_grp(ringA, bulkA, kg);
        fetch_grp(ringA, bulkA, kg + 2 * PFD);
        if (!bulkB) fetch_grp(ringB, bulkB, kg + PFD);    // late recheck
        consume_grp(ringB, bulkB, kg + PFD);
    }
    __syncthreads();

    // Epilogue: utility term from shortest paths (still in registers)
    float accU = 0.f;
#pragma unroll
    for (int lr = 0; lr < LROWS; lr++) {
        int r    = r0 + lr;
        float d  = dv[lr];
        float f  = flow[r * NN + t];
        float sp = wv[lr];
        float choice = 1.0f / (1.0f + expf(fmaf(0.005f, sp, -0.01f * d)));
        float ds  = fmaf(-0.5f, sp, d);
        float ug  = f * choice * ds;
        float elu = (ug > 0.f) ? ug : (expf(ug) - 1.0f);
        accU += elu + 1.0f;
    }

    // CTA reduction of the four partials
#pragma unroll
    for (int o = 16; o > 0; o >>= 1) {
        accC += __shfl_down_sync(0xffffffffu, accC, o);
        accU += __shfl_down_sync(0xffffffffu, accU, o);
        accE += __shfl_down_sync(0xffffffffu, accE, o);
        accM += __shfl_down_sync(0xffffffffu, accM, o);
    }
    if (lane == 0) { r4[wid][0] = accC; r4[wid][1] = accU; r4[wid][2] = accE; r4[wid][3] = accM; }
    __syncthreads();
    if (t < 16) {
        float a = r4[t][0], b = r4[t][1], c = r4[t][2], d = r4[t][3];
#pragma unroll
        for (int o = 8; o > 0; o >>= 1) {
            a += __shfl_down_sync(0xffffu, a, o);
            b += __shfl_down_sync(0xffffu, b, o);
            c += __shfl_down_sync(0xffffu, c, o);
            d += __shfl_down_sync(0xffffu, d, o);
        }
        if (t == 0) {
            g_part[cta * 4 + 0] = a; g_part[cta * 4 + 1] = b;
            g_part[cta * 4 + 2] = c; g_part[cta * 4 + 3] = d;
        }
    }

    // End-of-run state reset (last CTA) so the next graph replay starts clean.
    __threadfence();
    __syncthreads();
    if (t == 0) {
        int prev = atomicAdd(&g_done, 1);
        if (prev == NCTA - 1) {
            g_front = 0;
            __threadfence();
            g_done = 0;
        }
    }
}

__global__ void fin_kernel(const int* __restrict__ ep, float* __restrict__ out)
{
    const int t = threadIdx.x;           // 128 threads = NCTA
    const int lane = t & 31, wid = t >> 5;
    __shared__ float s4[4][4];
    float c = g_part[t * 4 + 0], u = g_part[t * 4 + 1];
    float e = g_part[t * 4 + 2], m = g_part[t * 4 + 3];
#pragma unroll
    for (int o = 16; o > 0; o >>= 1) {
        c += __shfl_down_sync(0xffffffffu, c, o);
        u += __shfl_down_sync(0xffffffffu, u, o);
        e += __shfl_down_sync(0xffffffffu, e, o);
        m += __shfl_down_sync(0xffffffffu, m, o);
    }
    if (lane == 0) { s4[wid][0] = c; s4[wid][1] = u; s4[wid][2] = e; s4[wid][3] = m; }
    __syncthreads();
    if (t == 0) {
        float C = s4[0][0] + s4[1][0] + s4[2][0] + s4[3][0];
        float U = s4[0][1] + s4[1][1] + s4[2][1] + s4[3][1];
        float E = s4[0][2] + s4[1][2] + s4[2][2] + s4[3][2];
        float M = s4[0][3] + s4[1][3] + s4[2][3] + s4[3][3];
        int epoch = *ep;
        int idx = (epoch >= 0) + (epoch >= 10) + (epoch >= 50);   // bisect_right([0,10,50], epoch)
        const float lv[4] = {0.0f, 0.05f, 0.1f, 1.0f};
        out[0] = C + U + lv[idx] * E + 10000.0f * M;
    }
}

extern "C" void kernel_launch(void* const* d_in, const int* in_sizes, int n_in,
                              void* d_out, int out_size)
{
    (void)in_sizes; (void)n_in; (void)out_size;
    const float* soft = (const float*)d_in[0];
    const float* orig = (const float*)d_in[1];
    const float* dist = (const float*)d_in[2];
    const float* flow = (const float*)d_in[3];
    const int*   ep   = (const int*)d_in[4];

    fw_kernel<<<NCTA, NTH>>>(soft, orig, dist, flow);
    fin_kernel<<<1, NCTA>>>(ep, (float*)d_out);
}